// round 3
// baseline (speedup 1.0000x reference)
#include <cuda_runtime.h>
#include <cstdint>

#define BB 64
#define NN 512
#define NROWS (BB*NN)            /* 32768 */
#define BNS 0.9995003746f        /* 1/sqrt(1+1e-3) */
#define EXC (-14.4269504089f)    /* -10*log2(e) */

/* ---------------- scratch: __device__ globals (no allocs allowed) -------- */
__device__ float g_feat0[NROWS * 64];
__device__ float g_feat1[NROWS * 64];
__device__ float g_mask[NROWS];
__device__ float g_S[NROWS];
__device__ float g_T[NROWS];
__device__ float g_part[512 * 64 * 128];
__device__ float g_h0[64 * 128];

__device__ __forceinline__ float ex2(float x) {
    float r;
    asm("ex2.approx.ftz.f32 %0, %1;" : "=f"(r) : "f"(x));
    return r;
}

/* ---------------- prep: embeddings + feature concat + mask --------------- */
__global__ void prep_kernel(const float* __restrict__ xx,
                            const float* __restrict__ e1,
                            const float* __restrict__ e2,
                            const float* __restrict__ e3) {
    int row = blockIdx.x * 256 + threadIdx.x;
    if (row >= NROWS) return;
    const float* xr = xx + (size_t)row * 30;
    float* fr = g_feat0 + (size_t)row * 64;
    g_mask[row] = xr[0];
    int i1 = (int)fabsf(xr[27]);
    int i2 = (int)fabsf(xr[28]);
    int i3 = (int)fabsf(xr[29]);
    fr[0] = e1[2 * i1];  fr[1] = e1[2 * i1 + 1];
    fr[2] = e2[2 * i2];  fr[3] = e2[2 * i2 + 1];
    fr[4] = e3[2 * i3];  fr[5] = e3[2 * i3 + 1];
#pragma unroll
    for (int c = 0; c < 27; c++) fr[6 + c] = xr[c];
}

/* ---------------- pairwise S/T kernel ------------------------------------ */
template <int ND>
__global__ void pair_kernel(int bufIn, int col0) {
    __shared__ float cs[ND][NN];
    const float* feat = bufIn ? g_feat1 : g_feat0;
    int b = blockIdx.y;
    int tid = threadIdx.x;           /* 256 */
    const float* fb = feat + (size_t)b * NN * 64;
    for (int idx = tid; idx < ND * NN; idx += 256) {
        int d = idx >> 9;            /* NN = 512 */
        int i = idx & (NN - 1);
        cs[d][i] = fb[i * 64 + col0 + d];
    }
    __syncthreads();
    int j = blockIdx.x * 256 + tid;
    float cj[ND];
#pragma unroll
    for (int d = 0; d < ND; d++) cj[d] = cs[d][j];
    float S0 = 0.f, S1 = 0.f, S2 = 0.f, S3 = 0.f, T0 = 0.f, T1 = 0.f;
#pragma unroll 4
    for (int i = 0; i < NN; i += 4) {
#pragma unroll
        for (int u = 0; u < 4; u++) {
            float d2 = 0.f;
#pragma unroll
            for (int d = 0; d < ND; d++) {
                float df = cs[d][i + u] - cj[d];
                d2 = fmaf(df, df, d2);
            }
            float w = ex2(EXC * d2);
            if (u == 0)      { S0 += w; T0 = fmaf(d2, w, T0); }
            else if (u == 1) { S1 += w; T1 = fmaf(d2, w, T1); }
            else if (u == 2) { S2 += w; T0 = fmaf(d2, w, T0); }
            else             { S3 += w; T1 = fmaf(d2, w, T1); }
        }
    }
    g_S[b * NN + j] = (S0 + S1) + (S2 + S3);
    g_T[b * NN + j] = T0 + T1;
}

/* ---------------- GNN layer: factored GEMM + epilogue --------------------
 * out_k = tanh( bn( mask * ( u_k + (mask*S - 1)*v_k + mask*T*a3_k + b_k ) ) )
 * u = x@A[0:Din], v = x@A[Din:2Din], a3 = A[2Din].
 * B-matrix in smem interleaved: col 2k = A1[:,k], col 2k+1 = A2[:,k].
 * Block: 32 rows x 128 interleaved cols, 256 threads, 4x4 microtile.
 */
__global__ void layer_kernel(int bufIn, int bufOut, int Din,
                             const float* __restrict__ A,
                             const float* __restrict__ bvec,
                             const float* __restrict__ gamma,
                             const float* __restrict__ beta) {
    __shared__ float As[64][128];    /* 32KB, d-major interleaved */
    __shared__ float xsT[64][32];    /* 8KB, [d][row] */
    __shared__ float a3s[64], bs[64], gs[64], bes[64];
    const float* featIn = bufIn ? g_feat1 : g_feat0;
    float* featOut = bufOut ? g_feat1 : g_feat0;
    int tid = threadIdx.x;           /* 256 */
    int row0 = blockIdx.x * 32;

    for (int idx = tid; idx < Din * 64; idx += 256) {
        int d = idx >> 6, k = idx & 63;
        As[d][2 * k]     = A[d * 64 + k];
        As[d][2 * k + 1] = A[(Din + d) * 64 + k];
    }
    if (tid < 64) {
        a3s[tid] = A[2 * Din * 64 + tid];
        bs[tid] = bvec[tid];
        gs[tid] = gamma[tid];
        bes[tid] = beta[tid];
    }
    for (int idx = tid; idx < 2048; idx += 256) {
        int d = idx >> 5, r = idx & 31;
        if (d < Din) xsT[d][r] = featIn[(size_t)(row0 + r) * 64 + d];
    }
    __syncthreads();

    int tx = tid & 31, ty = tid >> 5;    /* ty: 8 row-groups, tx: 32 col-groups */
    float acc[4][4];
#pragma unroll
    for (int r = 0; r < 4; r++)
#pragma unroll
        for (int c = 0; c < 4; c++) acc[r][c] = 0.f;

    for (int d = 0; d < Din; d++) {
        float4 av = *(const float4*)&xsT[d][ty * 4];   /* warp-broadcast */
        float4 bv = *(const float4*)&As[d][tx * 4];    /* conflict-free   */
        float a[4] = {av.x, av.y, av.z, av.w};
        float bb[4] = {bv.x, bv.y, bv.z, bv.w};
#pragma unroll
        for (int r = 0; r < 4; r++)
#pragma unroll
            for (int c = 0; c < 4; c++) acc[r][c] = fmaf(a[r], bb[c], acc[r][c]);
    }

#pragma unroll
    for (int rr = 0; rr < 4; rr++) {
        int row = row0 + ty * 4 + rr;
        float m = g_mask[row];
        float msm1 = fmaf(m, g_S[row], -1.f);
        float mt = m * g_T[row];
#pragma unroll
        for (int c = 0; c < 2; c++) {
            int k = tx * 2 + c;
            float val = acc[rr][2 * c] + msm1 * acc[rr][2 * c + 1]
                        + mt * a3s[k] + bs[k];
            val *= m;
            val = fmaf(gs[k] * BNS, val, bes[k]);
            featOut[(size_t)row * 64 + k] = tanhf(val);
        }
    }
}

/* ---------------- dense head -------------------------------------------- */
/* split-K partial GEMM: x(64,32768) @ dW0(32768,128); 512 blocks x K-slab 64 */
__global__ void dense0_partial(const float* __restrict__ dW0) {
    __shared__ float xs[64][64];     /* 16KB */
    int tid = threadIdx.x;           /* 128 */
    int k0 = blockIdx.x * 64;
    for (int idx = tid; idx < 64 * 64; idx += 128) {
        int m = idx >> 6, kk = idx & 63;
        xs[m][kk] = g_feat1[(size_t)m * 32768 + k0 + kk];
    }
    __syncthreads();
    float acc[64];
#pragma unroll
    for (int m = 0; m < 64; m++) acc[m] = 0.f;
    int n = tid;
    for (int kk = 0; kk < 64; kk++) {
        float w = dW0[(size_t)(k0 + kk) * 128 + n];
#pragma unroll
        for (int m = 0; m < 64; m++) acc[m] = fmaf(xs[m][kk], w, acc[m]);
    }
    float* p = g_part + (size_t)blockIdx.x * 8192;
#pragma unroll
    for (int m = 0; m < 64; m++) p[m * 128 + n] = acc[m];
}

/* deterministic fixed-order reduce + bias + bn + sigmoid */
__global__ void dense0_reduce(const float* __restrict__ db0,
                              const float* __restrict__ dg,
                              const float* __restrict__ dbt) {
    int idx = blockIdx.x * 256 + threadIdx.x;   /* 8192 */
    float s = 0.f;
    for (int p = 0; p < 512; p++) s += g_part[(size_t)p * 8192 + idx];
    int n = idx & 127;
    float v = s + db0[n];
    v = fmaf(dg[n] * BNS, v, dbt[n]);
    g_h0[idx] = 1.f / (1.f + expf(-v));
}

/* h0(64,128) @ dW1(128,128) -> sigmoid(bn) -> @ W2(128,2) + b2 -> out(64,4) */
__global__ void head_kernel(const float* __restrict__ dW1,
                            const float* __restrict__ db1,
                            const float* __restrict__ dg,
                            const float* __restrict__ dbt,
                            const float* __restrict__ W2,
                            const float* __restrict__ b2,
                            float* __restrict__ out) {
    __shared__ float h0[64][128];    /* 32KB */
    __shared__ float h1[16][128];    /* 8KB  */
    int tid = threadIdx.x;           /* 128 */
    int m0 = blockIdx.x * 16;
    for (int idx = tid; idx < 8192; idx += 128)
        h0[idx >> 7][idx & 127] = g_h0[idx];
    __syncthreads();
    int n = tid;
    float acc[16];
#pragma unroll
    for (int m = 0; m < 16; m++) acc[m] = db1[n];
    for (int k = 0; k < 128; k++) {
        float w = dW1[k * 128 + n];
#pragma unroll
        for (int m = 0; m < 16; m++) acc[m] = fmaf(h0[m0 + m][k], w, acc[m]);
    }
    float g = dg[128 + n] * BNS, bt = dbt[128 + n];
#pragma unroll
    for (int m = 0; m < 16; m++) {
        float v = fmaf(g, acc[m], bt);
        h1[m][n] = 1.f / (1.f + expf(-v));
    }
    __syncthreads();
    if (tid < 16) {
        int m = tid;
        float o0 = b2[0], o1 = b2[1];
        for (int nn = 0; nn < 128; nn++) {
            float h = h1[m][nn];
            o0 = fmaf(h, W2[2 * nn], o0);
            o1 = fmaf(h, W2[2 * nn + 1], o1);
        }
        out[(m0 + m) * 4 + 0] = o0;
        out[(m0 + m) * 4 + 1] = o1;
        out[(m0 + m) * 4 + 2] = 0.f;
        out[(m0 + m) * 4 + 3] = 0.f;
    }
}

/* ---------------- launch -------------------------------------------------- */
extern "C" void kernel_launch(void* const* d_in, const int* in_sizes, int n_in,
                              void* d_out, int out_size) {
    const float* xx        = (const float*)d_in[0];
    const float* emb1      = (const float*)d_in[1];
    const float* emb2      = (const float*)d_in[2];
    const float* emb3      = (const float*)d_in[3];
    const float* A0        = (const float*)d_in[4];
    const float* b0        = (const float*)d_in[5];
    const float* A_rest    = (const float*)d_in[6];
    const float* b_rest    = (const float*)d_in[7];
    const float* bn_gamma  = (const float*)d_in[8];
    const float* bn_beta   = (const float*)d_in[9];
    const float* dW0       = (const float*)d_in[10];
    const float* db0       = (const float*)d_in[11];
    const float* dW1       = (const float*)d_in[12];
    const float* db1       = (const float*)d_in[13];
    const float* dbn_gamma = (const float*)d_in[14];
    const float* dbn_beta  = (const float*)d_in[15];
    const float* W2        = (const float*)d_in[16];
    const float* b2        = (const float*)d_in[17];
    float* out = (float*)d_out;

    prep_kernel<<<NROWS / 256, 256>>>(xx, emb1, emb2, emb3);

    /* layer 0: Din=33, c = cols 31..32 */
    pair_kernel<2><<<dim3(2, BB), 256>>>(0, 31);
    layer_kernel<<<NROWS / 32, 256>>>(0, 1, 33, A0, b0, bn_gamma, bn_beta);

    /* layers 1..4: Din=64, c = cols 60..63; ping-pong f1->f0->f1->f0->f1 */
    for (int l = 1; l < 5; l++) {
        int in = l & 1;
        int outb = in ^ 1;
        pair_kernel<4><<<dim3(2, BB), 256>>>(in, 60);
        layer_kernel<<<NROWS / 32, 256>>>(in, outb, 64,
                                          A_rest + (size_t)(l - 1) * 129 * 64,
                                          b_rest + (size_t)(l - 1) * 64,
                                          bn_gamma + (size_t)l * 64,
                                          bn_beta + (size_t)l * 64);
    }

    /* dense head (final GNN output lives in g_feat1) */
    dense0_partial<<<512, 128>>>(dW0);
    dense0_reduce<<<32, 256>>>(db0, dbn_gamma, dbn_beta);
    head_kernel<<<4, 128>>>(dW1, db1, dbn_gamma, dbn_beta, W2, b2, out);
}